// round 16
// baseline (speedup 1.0000x reference)
#include <cuda_runtime.h>
#include <cuda_fp16.h>
#include <cstdint>
#include <math.h>

#define SQ 512
#define HD 512
#define NB 256
#define NTILES 4096   // 32 j-tiles x 64 i-tiles x 2 batch

// ---------------- device scratch ----------------
__device__ float g_a[1024 * 512];     // a = f@W1[:H] + b1 (folded)
__device__ float g_c[1024 * 512];     // c = f@W1[H:]
__device__ __half g_w2t[NB * HD];     // W2^T fp16 [n][k]

// ---------------- pair-kernel smem layout (bytes) ----------------
static constexpr int SM_A   = 0;        // [buf4][128 rows][128B]  4*16384 = 65536
static constexpr int SM_B   = 65536;    // [buf4][256 rows][128B]  4*32768 = 131072
static constexpr int SM_ACS = 196608;   // [buf4][24 rows][272B]   4*6528  = 26112
static constexpr int SM_B2  = 222720;   // 1024
static constexpr int SM_W3  = 223744;   // 1024
static constexpr int SM_PSM = 224768;   // 128*4 floats = 2048
static constexpr int SMEM_TOTAL = 226816;

__device__ __forceinline__ uint32_t smem_u32(const void* p) {
    uint32_t a;
    asm("{ .reg .u64 t; cvta.to.shared.u64 t, %1; cvt.u32.u64 %0, t; }" : "=r"(a) : "l"(p));
    return a;
}
__device__ __forceinline__ uint32_t sw128(uint32_t off) { return off ^ ((off >> 3) & 0x70); }
__device__ __forceinline__ uint32_t cvt_f16x2(float lo, float hi) {
    __half2 h = __floats2half2_rn(lo, hi);
    return *(uint32_t*)&h;
}

#define LDSM4(r, a) \
    asm volatile("ldmatrix.sync.aligned.m8n8.x4.shared.b16 {%0,%1,%2,%3}, [%4];" \
        : "=r"((r)[0]), "=r"((r)[1]), "=r"((r)[2]), "=r"((r)[3]) : "r"(a))

#define MMA16816(c, a, b0v, b1v) \
    asm volatile("mma.sync.aligned.m16n8k16.row.col.f32.f16.f16.f32 " \
        "{%0,%1,%2,%3}, {%4,%5,%6,%7}, {%8,%9}, {%0,%1,%2,%3};" \
        : "+f"((c)[0]), "+f"((c)[1]), "+f"((c)[2]), "+f"((c)[3]) \
        : "r"((a)[0]), "r"((a)[1]), "r"((a)[2]), "r"((a)[3]), "r"(b0v), "r"(b1v))

#define CP16(dst, src) \
    asm volatile("cp.async.cg.shared.global [%0], [%1], 16;" :: "r"(dst), "l"(src) : "memory")
#define CP_COMMIT()  asm volatile("cp.async.commit_group;" ::: "memory")
#define CP_WAIT1()   asm volatile("cp.async.wait_group 1;" ::: "memory")

#define BAR_SYNC(id, cnt)   asm volatile("bar.sync %0, %1;"   :: "r"(id), "r"(cnt) : "memory")
// barrier ids: 1=S (full 384, per 2-chunk window), 5=PROD (128), 6=CONS-EPI (256)

// tile index -> (bz, i0, j0); tile = x + 32*y + 2048*z
__device__ __forceinline__ void tile_decode(int tile, int& bz, int& i0, int& j0) {
    bz = tile >> 11;
    int rem = tile & 2047;
    i0 = (rem >> 5) * 8;
    j0 = (rem & 31) * 16;
}

// =====================================================================
// Kernel A: a/c projections (64x64 tiles, cp.async 3-stage, b1 folded)
// =====================================================================
__global__ __launch_bounds__(256) void gemm_ac_kernel(const float* __restrict__ f,
                                                      const float* __restrict__ W1,
                                                      const float* __restrict__ b1) {
    const int z = blockIdx.z;
    const float* W = W1 + (size_t)z * HD * HD;
    float* out = z ? g_c : g_a;
    const int m0 = blockIdx.y * 64;
    const int n0 = blockIdx.x * 64;

    __shared__ float fs[3][64][36];
    __shared__ float ws[3][32][64];

    const int tid = threadIdx.x;
    const int tx = tid & 15, ty = tid >> 4;

    auto pf = [&](int c) {
        int st = c % 3, k0 = c * 32;
#pragma unroll
        for (int u = 0; u < 2; ++u) {
            int s = u * 256 + tid;
            int m = s >> 3, g = s & 7;
            CP16(smem_u32(&fs[st][m][g * 4]), f + (size_t)(m0 + m) * HD + k0 + g * 4);
        }
#pragma unroll
        for (int u = 0; u < 2; ++u) {
            int s = u * 256 + tid;
            int kk = s >> 4, g = s & 15;
            CP16(smem_u32(&ws[st][kk][g * 4]), W + (size_t)(k0 + kk) * HD + n0 + g * 4);
        }
        CP_COMMIT();
    };

    pf(0); pf(1);

    float acc[4][4];
#pragma unroll
    for (int r = 0; r < 4; r++)
#pragma unroll
        for (int c = 0; c < 4; c++) acc[r][c] = 0.f;

    for (int c = 0; c < 16; ++c) {
        CP_WAIT1();
        __syncthreads();
        const int st = c % 3;
#pragma unroll
        for (int hh = 0; hh < 32; ++hh) {
            float fv[4];
#pragma unroll
            for (int r = 0; r < 4; r++) fv[r] = fs[st][ty * 4 + r][hh];
            float4 wv = *(const float4*)&ws[st][hh][tx * 4];
#pragma unroll
            for (int r = 0; r < 4; r++) {
                acc[r][0] += fv[r] * wv.x;
                acc[r][1] += fv[r] * wv.y;
                acc[r][2] += fv[r] * wv.z;
                acc[r][3] += fv[r] * wv.w;
            }
        }
        if (c + 2 < 16) pf(c + 2);
        else CP_COMMIT();
    }

    float4 bv = make_float4(0.f, 0.f, 0.f, 0.f);
    if (z == 0) bv = *(const float4*)&b1[n0 + tx * 4];
#pragma unroll
    for (int r = 0; r < 4; r++) {
        float4 o = make_float4(acc[r][0] + bv.x, acc[r][1] + bv.y,
                               acc[r][2] + bv.z, acc[r][3] + bv.w);
        *(float4*)&out[(size_t)(m0 + ty * 4 + r) * HD + n0 + tx * 4] = o;
    }
}

// =====================================================================
// Kernel B: W2 -> fp16 transposed [n][k]
// =====================================================================
__global__ void w2prep_kernel(const float* __restrict__ W2) {
    int base = blockIdx.x * 1024 + threadIdx.x * 4;
#pragma unroll
    for (int v = 0; v < 4; ++v) {
        int idx = base + v;
        int k = idx >> 8, n = idx & 255;
        g_w2t[n * HD + k] = __float2half_rn(W2[idx]);
    }
}

// =====================================================================
// Kernel C: PERSISTENT warp-specialized pair MLP, 2-chunk sync windows,
// consumer warp grid 2(M)x4(N) (warp tile 64x64) to halve B LDSM
// duplication. Producer side identical to round 15.
// =====================================================================
__global__ __launch_bounds__(384, 1) void pair_hmma_persist_kernel(
    const float* __restrict__ b2, const float* __restrict__ W3,
    const float* __restrict__ b3, float* __restrict__ out) {

    extern __shared__ char smem[];
    const int tid = threadIdx.x;
    const int bid = blockIdx.x;
    const int grid = gridDim.x;
    const int ntiles = (NTILES - bid + grid - 1) / grid;   // tiles: bid + k*grid
    if (ntiles <= 0) return;
    const int G = ntiles * 8;      // chunks
    const int W = G >> 1;          // 2-chunk windows
    const uint32_t smb = smem_u32(smem);

    float* b2s = (float*)(smem + SM_B2);
    float* w3s = (float*)(smem + SM_W3);
    float* psm = (float*)(smem + SM_PSM);

    if (tid < 256) {
        // ============ CONSUMERS: pure LDSM + MMA, 2M x 4N ============
        const int wid = tid >> 5, lid = tid & 31;
        const int wm = wid >> 2;          // 0..1 : 64-row half of M
        const int wn = wid & 3;           // 0..3 : 64-col quarter of N

        if (tid < 64) ((float4*)b2s)[tid] = ((const float4*)b2)[tid];
        else if (tid < 128) ((float4*)w3s)[tid - 64] = ((const float4*)W3)[tid - 64];
        const float b3v = __ldg(b3);

        float acc[4][8][4];
#pragma unroll
        for (int mf = 0; mf < 4; mf++)
#pragma unroll
            for (int nf = 0; nf < 8; nf++)
#pragma unroll
                for (int e = 0; e < 4; e++) acc[mf][nf][e] = 0.f;

        const uint32_t xorK = (uint32_t)((lid & 7) << 4);
        const uint32_t khb  = (uint32_t)((lid >> 4) << 4);
        const uint32_t rAb  = (uint32_t)(wm * 64 + (lid & 15));
        const uint32_t rBb  = (uint32_t)(wn * 64 + (lid & 15));

        for (int w = 0; w < W; ++w) {
            BAR_SYNC(1, 384);                 // S(w): A/B(2w), A/B(2w+1) published

#pragma unroll
            for (int half = 0; half < 2; ++half) {
                const int g = 2 * w + half;
                const uint32_t Ah = smb + SM_A + (uint32_t)(g & 3) * 16384;
                const uint32_t Bh = smb + SM_B + (uint32_t)(g & 3) * 32768;
#pragma unroll
                for (int ks = 0; ks < 4; ++ks) {
                    const uint32_t ko = ((uint32_t)(ks * 32) + khb) ^ xorK;
                    uint32_t af[4][4];
#pragma unroll
                    for (int mf = 0; mf < 4; ++mf)
                        LDSM4(af[mf], Ah + (rAb + mf * 16) * 128 + ko);
#pragma unroll
                    for (int nfp = 0; nfp < 4; ++nfp) {
                        uint32_t bf[4];
                        LDSM4(bf, Bh + (rBb + nfp * 16) * 128 + ko);
#pragma unroll
                        for (int mf = 0; mf < 4; ++mf) {
                            MMA16816(acc[mf][2 * nfp],     af[mf], bf[0], bf[2]);
                            MMA16816(acc[mf][2 * nfp + 1], af[mf], bf[1], bf[3]);
                        }
                    }
                }
            }

            if ((w & 3) == 3) {
                // ---- tile epilogue: relu(+b2).W3, reduce, psm, out ----
                float pr[4][2];
#pragma unroll
                for (int mf = 0; mf < 4; ++mf) { pr[mf][0] = 0.f; pr[mf][1] = 0.f; }
#pragma unroll
                for (int nf = 0; nf < 8; ++nf) {
                    const int n = wn * 64 + nf * 8 + 2 * (lid & 3);
                    const float b2x = b2s[n], b2y = b2s[n + 1];
                    const float w3x = w3s[n], w3y = w3s[n + 1];
#pragma unroll
                    for (int mf = 0; mf < 4; ++mf) {
                        pr[mf][0] += fmaxf(acc[mf][nf][0] + b2x, 0.f) * w3x
                                   + fmaxf(acc[mf][nf][1] + b2y, 0.f) * w3y;
                        pr[mf][1] += fmaxf(acc[mf][nf][2] + b2x, 0.f) * w3x
                                   + fmaxf(acc[mf][nf][3] + b2y, 0.f) * w3y;
                    }
                }
#pragma unroll
                for (int mf = 0; mf < 4; ++mf)
#pragma unroll
                    for (int h = 0; h < 2; ++h) {
                        pr[mf][h] += __shfl_xor_sync(0xffffffffu, pr[mf][h], 1);
                        pr[mf][h] += __shfl_xor_sync(0xffffffffu, pr[mf][h], 2);
                    }
                if ((lid & 3) == 0) {
#pragma unroll
                    for (int mf = 0; mf < 4; ++mf)
#pragma unroll
                        for (int h = 0; h < 2; ++h) {
                            int row = wm * 64 + mf * 16 + (lid >> 2) + h * 8;
                            psm[row * 4 + wn] = pr[mf][h];
                        }
                }
                BAR_SYNC(6, 256);              // consumer-only: psm visible
                if (tid < 128) {
                    int bz, i0, j0;
                    tile_decode(bid + (w >> 2) * grid, bz, i0, j0);
                    float lg = psm[tid * 4] + psm[tid * 4 + 1]
                             + psm[tid * 4 + 2] + psm[tid * 4 + 3] + b3v;
                    const int i = i0 + (tid >> 4);
                    const int j = j0 + (tid & 15);
                    out[((size_t)bz * SQ + i) * SQ + j] = 1.f / (1.f + __expf(-lg));
                }
#pragma unroll
                for (int mf = 0; mf < 4; mf++)
#pragma unroll
                    for (int nf = 0; nf < 8; nf++)
#pragma unroll
                        for (int e = 0; e < 4; e++) acc[mf][nf][e] = 0.f;
            }
        }
    } else {
        // ============ PRODUCERS: all cp.async + build (round-15 verbatim) ============
        const int p = tid - 256;              // 0..127
        const int iloc = p >> 4, jloc = p & 15;
        const uint32_t aXor = (uint32_t)((p & 7) << 4);

        auto issue_B = [&](int t) {           // 16 x 16B per thread (2048 lines)
            char* base = (char*)smem + SM_B + (t & 3) * 32768;
            const int chunk = t & 7;
#pragma unroll
            for (int v = 0; v < 16; ++v) {
                int s = v * 128 + p;
                int n = s >> 3, g = s & 7;
                uint32_t dst = smem_u32(base) + sw128((uint32_t)(n * 128 + g * 16));
                CP16(dst, g_w2t + (size_t)n * HD + chunk * 64 + g * 8);
            }
        };
        auto issue_acs = [&](int u) {         // 3 x 16B per thread (384 lines)
            const int chunk = u & 7;
            int bz, i0, j0;
            tile_decode(bid + (u >> 3) * grid, bz, i0, j0);
            char* acb = (char*)smem + SM_ACS + (u & 3) * 6528;
#pragma unroll
            for (int v = 0; v < 3; ++v) {
                int s = v * 128 + p;          // 24 rows x 16
                int row = s >> 4, g = s & 15;
                const float* src = (row < 8)
                    ? g_a + ((size_t)(bz * SQ + i0 + row)) * HD + chunk * 64 + g * 4
                    : g_c + ((size_t)(bz * SQ + j0 + (row - 8))) * HD + chunk * 64 + g * 4;
                uint32_t dst = smem_u32(acb) + (uint32_t)(row * 272 + g * 16);
                CP16(dst, src);
            }
        };
        auto build_A = [&](int u) {
            const char* acb = (const char*)smem + SM_ACS + (u & 3) * 6528;
            const float* arow = (const float*)(acb + iloc * 272);
            const float* crow = (const float*)(acb + (8 + jloc) * 272);
            uint32_t hv[32];
#pragma unroll
            for (int q = 0; q < 16; ++q) {
                float4 av = *(const float4*)(arow + q * 4);
                float4 cv = *(const float4*)(crow + q * 4);
                float v0 = fmaxf(av.x + cv.x, 0.f);
                float v1 = fmaxf(av.y + cv.y, 0.f);
                float v2 = fmaxf(av.z + cv.z, 0.f);
                float v3 = fmaxf(av.w + cv.w, 0.f);
                hv[q * 2]     = cvt_f16x2(v0, v1);
                hv[q * 2 + 1] = cvt_f16x2(v2, v3);
            }
            char* ah = (char*)smem + SM_A + (u & 3) * 16384;
#pragma unroll
            for (int s = 0; s < 8; ++s) {
                uint32_t off = (uint32_t)(p * 128) + (((uint32_t)(s * 16)) ^ aXor);
                *(uint4*)(ah + off) = make_uint4(hv[s*4], hv[s*4+1], hv[s*4+2], hv[s*4+3]);
            }
        };

        // prologue: P1 = B(0),B(1),acs(0),acs(1); P2 = acs(2),acs(3)
        issue_B(0);
        if (G > 1) issue_B(1);
        issue_acs(0);
        if (G > 1) issue_acs(1);
        CP_COMMIT();
        if (G > 2) issue_acs(2);
        if (G > 3) issue_acs(3);
        CP_COMMIT();
        CP_WAIT1();                           // P1 landed
        BAR_SYNC(5, 128);                     // acs(0),acs(1) visible across producers
        build_A(0);
        if (G > 1) build_A(1);
        BAR_SYNC(1, 384);                     // S(0)

        for (int w = 0; w < W; ++w) {
            if (2 * w + 2 < G) issue_B(2 * w + 2);
            if (2 * w + 3 < G) issue_B(2 * w + 3);
            CP_COMMIT();                      // group B_w
            if (2 * w + 4 < G) issue_acs(2 * w + 4);
            if (2 * w + 5 < G) issue_acs(2 * w + 5);
            CP_COMMIT();                      // group A_w
            CP_WAIT1();                       // B_w + acs(2w+2),acs(2w+3) landed
            BAR_SYNC(5, 128);                 // cross-producer acs visibility
            if (2 * w + 2 < G) build_A(2 * w + 2);
            if (2 * w + 3 < G) build_A(2 * w + 3);
            if (w < W - 1) BAR_SYNC(1, 384);  // S(w+1)
        }
    }
}

// =====================================================================
extern "C" void kernel_launch(void* const* d_in, const int* in_sizes, int n_in,
                              void* d_out, int out_size) {
    const float* f  = (const float*)d_in[0];
    const float* W1 = (const float*)d_in[1];
    const float* b1 = (const float*)d_in[2];
    const float* W2 = (const float*)d_in[3];
    const float* b2 = (const float*)d_in[4];
    const float* W3 = (const float*)d_in[5];
    const float* b3 = (const float*)d_in[6];
    float* out = (float*)d_out;

    static int nsm = 0;
    if (nsm == 0) {
        int dev = 0;
        cudaGetDevice(&dev);
        cudaDeviceGetAttribute(&nsm, cudaDevAttrMultiProcessorCount, dev);
        if (nsm <= 0) nsm = 148;
    }

    cudaFuncSetAttribute(pair_hmma_persist_kernel,
                         cudaFuncAttributeMaxDynamicSharedMemorySize, SMEM_TOTAL);

    gemm_ac_kernel<<<dim3(8, 16, 2), 256>>>(f, W1, b1);
    w2prep_kernel<<<128, 256>>>(W2);
    pair_hmma_persist_kernel<<<nsm, 384, SMEM_TOTAL>>>(b2, W3, b3, out);
}

// round 17
// speedup vs baseline: 1.1465x; 1.1465x over previous
#include <cuda_runtime.h>
#include <cuda_fp16.h>
#include <cstdint>
#include <math.h>

#define SQ 512
#define HD 512
#define NB 256
#define NTILES 4096   // 32 j-tiles x 64 i-tiles x 2 batch

// ---------------- device scratch ----------------
__device__ float g_a[1024 * 512];     // a = f@W1[:H] + b1 (folded)
__device__ float g_c[1024 * 512];     // c = f@W1[H:]
__device__ __half g_w2t[NB * HD];     // W2^T fp16 [n][k]

// ---------------- pair-kernel smem layout (bytes) ----------------
static constexpr int SM_A   = 0;        // [buf4][128 rows][128B]  4*16384 = 65536
static constexpr int SM_B   = 65536;    // [buf4][256 rows][128B]  4*32768 = 131072
static constexpr int SM_ACS = 196608;   // [buf4][24 rows][272B]   4*6528  = 26112
static constexpr int SM_B2  = 222720;   // 1024
static constexpr int SM_W3  = 223744;   // 1024
static constexpr int SM_PSM = 224768;   // 1024
static constexpr int SMEM_TOTAL = 225792;

__device__ __forceinline__ uint32_t smem_u32(const void* p) {
    uint32_t a;
    asm("{ .reg .u64 t; cvta.to.shared.u64 t, %1; cvt.u32.u64 %0, t; }" : "=r"(a) : "l"(p));
    return a;
}
__device__ __forceinline__ uint32_t sw128(uint32_t off) { return off ^ ((off >> 3) & 0x70); }
__device__ __forceinline__ uint32_t cvt_f16x2(float lo, float hi) {
    __half2 h = __floats2half2_rn(lo, hi);
    return *(uint32_t*)&h;
}

#define LDSM4(r, a) \
    asm volatile("ldmatrix.sync.aligned.m8n8.x4.shared.b16 {%0,%1,%2,%3}, [%4];" \
        : "=r"((r)[0]), "=r"((r)[1]), "=r"((r)[2]), "=r"((r)[3]) : "r"(a))

#define MMA16816(c, a, b0v, b1v) \
    asm volatile("mma.sync.aligned.m16n8k16.row.col.f32.f16.f16.f32 " \
        "{%0,%1,%2,%3}, {%4,%5,%6,%7}, {%8,%9}, {%0,%1,%2,%3};" \
        : "+f"((c)[0]), "+f"((c)[1]), "+f"((c)[2]), "+f"((c)[3]) \
        : "r"((a)[0]), "r"((a)[1]), "r"((a)[2]), "r"((a)[3]), "r"(b0v), "r"(b1v))

#define CP16(dst, src) \
    asm volatile("cp.async.cg.shared.global [%0], [%1], 16;" :: "r"(dst), "l"(src) : "memory")
#define CP_COMMIT()  asm volatile("cp.async.commit_group;" ::: "memory")
#define CP_WAIT1()   asm volatile("cp.async.wait_group 1;" ::: "memory")

#define BAR_SYNC(id, cnt)   asm volatile("bar.sync %0, %1;"   :: "r"(id), "r"(cnt) : "memory")
// barrier ids: 1=S (full 384, per 2-chunk window), 5=PROD (128), 6=CONS-EPI (256)

// tile index -> (bz, i0, j0); tile = x + 32*y + 2048*z
__device__ __forceinline__ void tile_decode(int tile, int& bz, int& i0, int& j0) {
    bz = tile >> 11;
    int rem = tile & 2047;
    i0 = (rem >> 5) * 8;
    j0 = (rem & 31) * 16;
}

// =====================================================================
// Kernel A: a/c projections (64x64 tiles, cp.async 3-stage, b1 folded)
// =====================================================================
__global__ __launch_bounds__(256) void gemm_ac_kernel(const float* __restrict__ f,
                                                      const float* __restrict__ W1,
                                                      const float* __restrict__ b1) {
    const int z = blockIdx.z;
    const float* W = W1 + (size_t)z * HD * HD;
    float* out = z ? g_c : g_a;
    const int m0 = blockIdx.y * 64;
    const int n0 = blockIdx.x * 64;

    __shared__ float fs[3][64][36];
    __shared__ float ws[3][32][64];

    const int tid = threadIdx.x;
    const int tx = tid & 15, ty = tid >> 4;

    auto pf = [&](int c) {
        int st = c % 3, k0 = c * 32;
#pragma unroll
        for (int u = 0; u < 2; ++u) {
            int s = u * 256 + tid;
            int m = s >> 3, g = s & 7;
            CP16(smem_u32(&fs[st][m][g * 4]), f + (size_t)(m0 + m) * HD + k0 + g * 4);
        }
#pragma unroll
        for (int u = 0; u < 2; ++u) {
            int s = u * 256 + tid;
            int kk = s >> 4, g = s & 15;
            CP16(smem_u32(&ws[st][kk][g * 4]), W + (size_t)(k0 + kk) * HD + n0 + g * 4);
        }
        CP_COMMIT();
    };

    pf(0); pf(1);

    float acc[4][4];
#pragma unroll
    for (int r = 0; r < 4; r++)
#pragma unroll
        for (int c = 0; c < 4; c++) acc[r][c] = 0.f;

    for (int c = 0; c < 16; ++c) {
        CP_WAIT1();
        __syncthreads();
        const int st = c % 3;
#pragma unroll
        for (int hh = 0; hh < 32; ++hh) {
            float fv[4];
#pragma unroll
            for (int r = 0; r < 4; r++) fv[r] = fs[st][ty * 4 + r][hh];
            float4 wv = *(const float4*)&ws[st][hh][tx * 4];
#pragma unroll
            for (int r = 0; r < 4; r++) {
                acc[r][0] += fv[r] * wv.x;
                acc[r][1] += fv[r] * wv.y;
                acc[r][2] += fv[r] * wv.z;
                acc[r][3] += fv[r] * wv.w;
            }
        }
        if (c + 2 < 16) pf(c + 2);
        else CP_COMMIT();
    }

    float4 bv = make_float4(0.f, 0.f, 0.f, 0.f);
    if (z == 0) bv = *(const float4*)&b1[n0 + tx * 4];
#pragma unroll
    for (int r = 0; r < 4; r++) {
        float4 o = make_float4(acc[r][0] + bv.x, acc[r][1] + bv.y,
                               acc[r][2] + bv.z, acc[r][3] + bv.w);
        *(float4*)&out[(size_t)(m0 + ty * 4 + r) * HD + n0 + tx * 4] = o;
    }
}

// =====================================================================
// Kernel B: W2 -> fp16 transposed [n][k]
// =====================================================================
__global__ void w2prep_kernel(const float* __restrict__ W2) {
    int base = blockIdx.x * 1024 + threadIdx.x * 4;
#pragma unroll
    for (int v = 0; v < 4; ++v) {
        int idx = base + v;
        int k = idx >> 8, n = idx & 255;
        g_w2t[n * HD + k] = __float2half_rn(W2[idx]);
    }
}

// =====================================================================
// Kernel C: PERSISTENT warp-specialized pair MLP, 2-chunk sync windows
// (round-15 structure), consumer grid 4(M)x2(N) with register
// double-buffered B fragments to hide LDSM->MMA latency.
// =====================================================================
__global__ __launch_bounds__(384, 1) void pair_hmma_persist_kernel(
    const float* __restrict__ b2, const float* __restrict__ W3,
    const float* __restrict__ b3, float* __restrict__ out) {

    extern __shared__ char smem[];
    const int tid = threadIdx.x;
    const int bid = blockIdx.x;
    const int grid = gridDim.x;
    const int ntiles = (NTILES - bid + grid - 1) / grid;   // tiles: bid + k*grid
    if (ntiles <= 0) return;
    const int G = ntiles * 8;      // chunks
    const int W = G >> 1;          // 2-chunk windows
    const uint32_t smb = smem_u32(smem);

    float* b2s = (float*)(smem + SM_B2);
    float* w3s = (float*)(smem + SM_W3);
    float* psm = (float*)(smem + SM_PSM);

    if (tid < 256) {
        // ============ CONSUMERS: pure LDSM + MMA, 4M x 2N ============
        const int wid = tid >> 5, lid = tid & 31;
        const int wm = wid >> 1, wn = wid & 1;

        if (tid < 64) ((float4*)b2s)[tid] = ((const float4*)b2)[tid];
        else if (tid < 128) ((float4*)w3s)[tid - 64] = ((const float4*)W3)[tid - 64];
        const float b3v = __ldg(b3);

        float acc[2][16][4];
#pragma unroll
        for (int mf = 0; mf < 2; mf++)
#pragma unroll
            for (int nf = 0; nf < 16; nf++)
#pragma unroll
                for (int e = 0; e < 4; e++) acc[mf][nf][e] = 0.f;

        const int rA = wm * 32 + (lid & 15);
        const uint32_t xorA = (uint32_t)((rA & 7) << 4);
        const int rB = wn * 128 + (lid & 15);
        const uint32_t xorB = (uint32_t)((rB & 7) << 4);
        const uint32_t khb = (uint32_t)((lid >> 4) << 4);

        for (int w = 0; w < W; ++w) {
            BAR_SYNC(1, 384);                 // S(w): A/B(2w), A/B(2w+1) published

#pragma unroll
            for (int half = 0; half < 2; ++half) {
                const int g = 2 * w + half;
                const uint32_t Ah = smb + SM_A + (uint32_t)(g & 3) * 16384;
                const uint32_t Bh = smb + SM_B + (uint32_t)(g & 3) * 32768;
#pragma unroll
                for (int ks = 0; ks < 4; ++ks) {
                    const uint32_t koff = ((uint32_t)(ks * 32) + khb);
                    const uint32_t aoff = (uint32_t)(rA * 128) + (koff ^ xorA);
                    uint32_t ah0[4], ah1[4];
                    LDSM4(ah0, Ah + aoff);
                    LDSM4(ah1, Ah + aoff + 16 * 128);
                    const uint32_t bko = koff ^ xorB;
                    // register double-buffered B fragments
                    uint32_t bh[2][4];
                    LDSM4(bh[0], Bh + (uint32_t)(rB * 128) + bko);
#pragma unroll
                    for (int nfp = 0; nfp < 8; ++nfp) {
                        const int cur = nfp & 1;
                        if (nfp < 7)
                            LDSM4(bh[cur ^ 1],
                                  Bh + (uint32_t)((rB + (nfp + 1) * 16) * 128) + bko);
                        MMA16816(acc[0][2 * nfp],     ah0, bh[cur][0], bh[cur][2]);
                        MMA16816(acc[0][2 * nfp + 1], ah0, bh[cur][1], bh[cur][3]);
                        MMA16816(acc[1][2 * nfp],     ah1, bh[cur][0], bh[cur][2]);
                        MMA16816(acc[1][2 * nfp + 1], ah1, bh[cur][1], bh[cur][3]);
                    }
                }
            }

            if ((w & 3) == 3) {
                // ---- tile epilogue: relu(+b2).W3, reduce, psm, out ----
                float pr[2][2] = {{0.f, 0.f}, {0.f, 0.f}};
#pragma unroll
                for (int nf = 0; nf < 16; ++nf) {
                    const int n = wn * 128 + nf * 8 + 2 * (lid & 3);
                    const float b2x = b2s[n], b2y = b2s[n + 1];
                    const float w3x = w3s[n], w3y = w3s[n + 1];
#pragma unroll
                    for (int mf = 0; mf < 2; ++mf) {
                        pr[mf][0] += fmaxf(acc[mf][nf][0] + b2x, 0.f) * w3x
                                   + fmaxf(acc[mf][nf][1] + b2y, 0.f) * w3y;
                        pr[mf][1] += fmaxf(acc[mf][nf][2] + b2x, 0.f) * w3x
                                   + fmaxf(acc[mf][nf][3] + b2y, 0.f) * w3y;
                    }
                }
#pragma unroll
                for (int mf = 0; mf < 2; ++mf)
#pragma unroll
                    for (int h = 0; h < 2; ++h) {
                        pr[mf][h] += __shfl_xor_sync(0xffffffffu, pr[mf][h], 1);
                        pr[mf][h] += __shfl_xor_sync(0xffffffffu, pr[mf][h], 2);
                    }
                if ((lid & 3) == 0) {
#pragma unroll
                    for (int mf = 0; mf < 2; ++mf)
#pragma unroll
                        for (int h = 0; h < 2; ++h) {
                            int row = wm * 32 + mf * 16 + (lid >> 2) + h * 8;
                            psm[row * 2 + wn] = pr[mf][h];
                        }
                }
                BAR_SYNC(6, 256);              // consumer-only: psm visible
                if (tid < 128) {
                    int bz, i0, j0;
                    tile_decode(bid + (w >> 2) * grid, bz, i0, j0);
                    float lg = psm[tid * 2] + psm[tid * 2 + 1] + b3v;
                    const int i = i0 + (tid >> 4);
                    const int j = j0 + (tid & 15);
                    out[((size_t)bz * SQ + i) * SQ + j] = 1.f / (1.f + __expf(-lg));
                }
#pragma unroll
                for (int mf = 0; mf < 2; mf++)
#pragma unroll
                    for (int nf = 0; nf < 16; nf++)
#pragma unroll
                        for (int e = 0; e < 4; e++) acc[mf][nf][e] = 0.f;
            }
        }
    } else {
        // ============ PRODUCERS: all cp.async + build (round-15 verbatim) ============
        const int p = tid - 256;              // 0..127
        const int iloc = p >> 4, jloc = p & 15;
        const uint32_t aXor = (uint32_t)((p & 7) << 4);

        auto issue_B = [&](int t) {           // 16 x 16B per thread (2048 lines)
            char* base = (char*)smem + SM_B + (t & 3) * 32768;
            const int chunk = t & 7;
#pragma unroll
            for (int v = 0; v < 16; ++v) {
                int s = v * 128 + p;
                int n = s >> 3, g = s & 7;
                uint32_t dst = smem_u32(base) + sw128((uint32_t)(n * 128 + g * 16));
                CP16(dst, g_w2t + (size_t)n * HD + chunk * 64 + g * 8);
            }
        };
        auto issue_acs = [&](int u) {         // 3 x 16B per thread (384 lines)
            const int chunk = u & 7;
            int bz, i0, j0;
            tile_decode(bid + (u >> 3) * grid, bz, i0, j0);
            char* acb = (char*)smem + SM_ACS + (u & 3) * 6528;
#pragma unroll
            for (int v = 0; v < 3; ++v) {
                int s = v * 128 + p;          // 24 rows x 16
                int row = s >> 4, g = s & 15;
                const float* src = (row < 8)
                    ? g_a + ((size_t)(bz * SQ + i0 + row)) * HD + chunk * 64 + g * 4
                    : g_c + ((size_t)(bz * SQ + j0 + (row - 8))) * HD + chunk * 64 + g * 4;
                uint32_t dst = smem_u32(acb) + (uint32_t)(row * 272 + g * 16);
                CP16(dst, src);
            }
        };
        auto build_A = [&](int u) {
            const char* acb = (const char*)smem + SM_ACS + (u & 3) * 6528;
            const float* arow = (const float*)(acb + iloc * 272);
            const float* crow = (const float*)(acb + (8 + jloc) * 272);
            uint32_t hv[32];
#pragma unroll
            for (int q = 0; q < 16; ++q) {
                float4 av = *(const float4*)(arow + q * 4);
                float4 cv = *(const float4*)(crow + q * 4);
                float v0 = fmaxf(av.x + cv.x, 0.f);
                float v1 = fmaxf(av.y + cv.y, 0.f);
                float v2 = fmaxf(av.z + cv.z, 0.f);
                float v3 = fmaxf(av.w + cv.w, 0.f);
                hv[q * 2]     = cvt_f16x2(v0, v1);
                hv[q * 2 + 1] = cvt_f16x2(v2, v3);
            }
            char* ah = (char*)smem + SM_A + (u & 3) * 16384;
#pragma unroll
            for (int s = 0; s < 8; ++s) {
                uint32_t off = (uint32_t)(p * 128) + (((uint32_t)(s * 16)) ^ aXor);
                *(uint4*)(ah + off) = make_uint4(hv[s*4], hv[s*4+1], hv[s*4+2], hv[s*4+3]);
            }
        };

        // prologue: P1 = B(0),B(1),acs(0),acs(1); P2 = acs(2),acs(3)
        issue_B(0);
        if (G > 1) issue_B(1);
        issue_acs(0);
        if (G > 1) issue_acs(1);
        CP_COMMIT();
        if (G > 2) issue_acs(2);
        if (G > 3) issue_acs(3);
        CP_COMMIT();
        CP_WAIT1();                           // P1 landed
        BAR_SYNC(5, 128);                     // acs(0),acs(1) visible across producers
        build_A(0);
        if (G > 1) build_A(1);
        BAR_SYNC(1, 384);                     // S(0)

        for (int w = 0; w < W; ++w) {
            if (2 * w + 2 < G) issue_B(2 * w + 2);
            if (2 * w + 3 < G) issue_B(2 * w + 3);
            CP_COMMIT();                      // group B_w
            if (2 * w + 4 < G) issue_acs(2 * w + 4);
            if (2 * w + 5 < G) issue_acs(2 * w + 5);
            CP_COMMIT();                      // group A_w
            CP_WAIT1();                       // B_w + acs(2w+2),acs(2w+3) landed
            BAR_SYNC(5, 128);                 // cross-producer acs visibility
            if (2 * w + 2 < G) build_A(2 * w + 2);
            if (2 * w + 3 < G) build_A(2 * w + 3);
            if (w < W - 1) BAR_SYNC(1, 384);  // S(w+1)
        }
    }
}

// =====================================================================
extern "C" void kernel_launch(void* const* d_in, const int* in_sizes, int n_in,
                              void* d_out, int out_size) {
    const float* f  = (const float*)d_in[0];
    const float* W1 = (const float*)d_in[1];
    const float* b1 = (const float*)d_in[2];
    const float* W2 = (const float*)d_in[3];
    const float* b2 = (const float*)d_in[4];
    const float* W3 = (const float*)d_in[5];
    const float* b3 = (const float*)d_in[6];
    float* out = (float*)d_out;

    static int nsm = 0;
    if (nsm == 0) {
        int dev = 0;
        cudaGetDevice(&dev);
        cudaDeviceGetAttribute(&nsm, cudaDevAttrMultiProcessorCount, dev);
        if (nsm <= 0) nsm = 148;
    }

    cudaFuncSetAttribute(pair_hmma_persist_kernel,
                         cudaFuncAttributeMaxDynamicSharedMemorySize, SMEM_TOTAL);

    gemm_ac_kernel<<<dim3(8, 16, 2), 256>>>(f, W1, b1);
    w2prep_kernel<<<128, 256>>>(W2);
    pair_hmma_persist_kernel<<<nsm, 384, SMEM_TOTAL>>>(b2, W3, b3, out);
}